// round 1
// baseline (speedup 1.0000x reference)
#include <cuda_runtime.h>

// OrbitalAEVComputer: coefficients [64,256,45] f32 -> out [64,256,4608] f32
// Per (conf,atom): 12 AOVs (4 p + 8 reordered d), radial 12*32, angular 66*8*8.

#define NBLOCKS (64 * 256)
#define OUT_STRIDE 4608
#define NPAIR 66

// cos/sin of shfZ = linspace(0.19634954, 2.94524311, 8)  (odd multiples of pi/16)
__constant__ float COSZ[8] = {
     0.98078528f,  0.83146961f,  0.55557023f,  0.19509032f,
    -0.19509032f, -0.55557023f, -0.83146961f, -0.98078528f
};
__constant__ float SINZ[8] = {
     0.19509032f,  0.55557023f,  0.83146961f,  0.98078528f,
     0.98078528f,  0.83146961f,  0.55557023f,  0.19509032f
};

// triu_indices(12, k=1), i-major
__constant__ unsigned char IU[NPAIR] = {
    0,0,0,0,0,0,0,0,0,0,0,
    1,1,1,1,1,1,1,1,1,1,
    2,2,2,2,2,2,2,2,2,
    3,3,3,3,3,3,3,3,
    4,4,4,4,4,4,4,
    5,5,5,5,5,5,
    6,6,6,6,6,
    7,7,7,7,
    8,8,8,
    9,9,
    10
};
__constant__ unsigned char JU[NPAIR] = {
    1,2,3,4,5,6,7,8,9,10,11,
    2,3,4,5,6,7,8,9,10,11,
    3,4,5,6,7,8,9,10,11,
    4,5,6,7,8,9,10,11,
    5,6,7,8,9,10,11,
    6,7,8,9,10,11,
    7,8,9,10,11,
    8,9,10,11,
    9,10,11,
    10,11,
    11
};

__global__ __launch_bounds__(128, 8)
void orbital_aev_kernel(const float* __restrict__ coeff, float* __restrict__ out)
{
    __shared__ float dsh[12];
    __shared__ float nvsh[12][3];
    __shared__ float czsh[NPAIR];
    __shared__ float szsh[NPAIR];
    __shared__ float avsh[NPAIR];

    const int atom = blockIdx.x;
    const int t = threadIdx.x;
    const float* __restrict__ c = coeff + (size_t)atom * 45;
    float* __restrict__ o = out + (size_t)atom * OUT_STRIDE;

    // ---- Build 12 AOVs: dist + normalized vectors into SMEM ----
    if (t < 12) {
        float x, y, z;
        if (t < 4) {
            int b = 9 + 3 * t;
            x = c[b]; y = c[b + 1]; z = c[b + 2];
        } else {
            int r = (t - 4) >> 1;
            int b = 21 + 6 * r;
            if (((t - 4) & 1) == 0) {        // d row picks [0,2,5]
                x = c[b];     y = c[b + 2]; z = c[b + 5];
            } else {                          // then [4,3,1]
                x = c[b + 4]; y = c[b + 3]; z = c[b + 1];
            }
        }
        float s = x * x + y * y + z * z;
        float inv, d;
        if (s > 1e-24f) { inv = rsqrtf(s); d = s * inv; }
        else            { inv = 0.0f;      d = 0.0f;    }
        dsh[t] = d;
        nvsh[t][0] = x * inv;
        nvsh[t][1] = y * inv;
        nvsh[t][2] = z * inv;
    }
    __syncthreads();

    // ---- Pair quantities: cz = 0.95*cos, sz = sin(acos(.)) = sqrt(1-cz^2), avdist ----
    if (t < NPAIR) {
        int i = IU[t], j = JU[t];
        float cc = nvsh[i][0] * nvsh[j][0]
                 + nvsh[i][1] * nvsh[j][1]
                 + nvsh[i][2] * nvsh[j][2];
        float cz = 0.95f * cc;
        float sz = sqrtf(fmaxf(0.0f, 1.0f - cz * cz));
        czsh[t] = cz;
        szsh[t] = sz;
        avsh[t] = 0.5f * (dsh[i] + dsh[j]);
    }

    // ---- Radial: s_aev == r_aev (same shifts, same eta) -> 192 unique exps, write twice ----
    // task m in [0,192): aov = m>>4, k = m&15; shf = 0.5 + 0.2*k
    #pragma unroll
    for (int m = t; m < 192; m += 128) {
        int aov = m >> 4;
        int k   = m & 15;
        float d = dsh[aov];
        float u = d - (0.5f + 0.2f * (float)k);
        float v = __expf(-16.0f * u * u);
        int base = (aov << 5) + k;
        o[base]      = v;   // s_aev slot
        o[base + 16] = v;   // r_aev slot (identical)
    }
    __syncthreads();

    // ---- Angular: 528 tasks (pair,z). Each task also owns f2 for a==z of its pair,
    //      exchanged within the 8-lane group via shuffles (groups are warp-aligned). ----
    #pragma unroll
    for (int iter = 0; iter < 5; iter++) {
        int m = t + 128 * iter;            // task id
        bool active = (m < 528);
        int mm = active ? m : 0;
        int p = mm >> 3;                   // pair
        int z = mm & 7;                    // shfZ index; doubles as shfA index for f2own

        // factor2 for (pair p, shfA index z)
        float av = avsh[p];
        float ua = av - (0.5f + (3.0f / 7.0f) * (float)z);
        float f2own = __expf(-8.0f * ua * ua);

        // factor1 for (pair p, shfZ index z): cos(angle - shfZ) via identity
        float cz = czsh[p];
        float sz = szsh[p];
        float cosd = fmaf(cz, COSZ[z], sz * SINZ[z]);
        float b = fmaf(0.5f, cosd, 0.5f);  // (1+cosd)/2 in [0,1]
        float q = b * b;                   // ^2
        q *= q;                            // ^4
        q *= q;                            // ^8
        q *= q;                            // ^16
        q *= q;                            // ^32
        float g = 2.0f * q;

        // gather the 8 f2 values of this pair from the 8-lane group
        int lane = t & 31;
        int gbase = lane & ~7;
        float f0 = __shfl_sync(0xffffffffu, f2own, gbase + 0);
        float f1 = __shfl_sync(0xffffffffu, f2own, gbase + 1);
        float f2 = __shfl_sync(0xffffffffu, f2own, gbase + 2);
        float f3 = __shfl_sync(0xffffffffu, f2own, gbase + 3);
        float f4 = __shfl_sync(0xffffffffu, f2own, gbase + 4);
        float f5 = __shfl_sync(0xffffffffu, f2own, gbase + 5);
        float f6 = __shfl_sync(0xffffffffu, f2own, gbase + 6);
        float f7 = __shfl_sync(0xffffffffu, f2own, gbase + 7);

        if (active) {
            float4 o0 = make_float4(g * f0, g * f1, g * f2, g * f3);
            float4 o1 = make_float4(g * f4, g * f5, g * f6, g * f7);
            float4* dst = reinterpret_cast<float4*>(o + 384 + (m << 3));
            dst[0] = o0;
            dst[1] = o1;
        }
    }
}

extern "C" void kernel_launch(void* const* d_in, const int* in_sizes, int n_in,
                              void* d_out, int out_size)
{
    const float* coeff = (const float*)d_in[0];
    float* out = (float*)d_out;
    orbital_aev_kernel<<<NBLOCKS, 128>>>(coeff, out);
}